// round 11
// baseline (speedup 1.0000x reference)
#include <cuda_runtime.h>
#include <cstdint>

// Entmax (alpha=1.5) per row, B=2048 x N=32000 fp32.
// v10 = v9 (single 125 KB smem buffer, in-place half-row TMA re-arm, chunked
// bulk copies, max-tree filter) +
//   - dynamic row tickets (atomic counter, fetched 1 row ahead) -> perfect
//     load balance across 152 CTAs; last CTA resets counters for graph replay
//   - all-warp redundant Newton on the candidate set -> no publish barrier

#define NC        32000
#define NV        (NC / 4)       // 8000 float4
#define NVH_      4000           // float4 per half
#define TPB       1024
#define VPT       8
#define VPH       4
#define CAP       1024
#define NEG       (-1e30f)
#define HALF_BYTES 64000
#define CHUNKS    4
#define CHUNK_B   (HALF_BYTES / CHUNKS)   // 16000

__device__ int g_next = 0;   // row tickets beyond the first wave
__device__ int g_done = 0;   // CTA completion count (for replay reset)

__device__ __forceinline__ uint32_t smem_u32(const void* p) {
    uint32_t a;
    asm("{ .reg .u64 t; cvta.to.shared.u64 t, %1; cvt.u32.u64 %0, t; }"
        : "=r"(a) : "l"(p));
    return a;
}
__device__ __forceinline__ void mbar_init(uint32_t a, uint32_t cnt) {
    asm volatile("mbarrier.init.shared.b64 [%0], %1;" :: "r"(a), "r"(cnt) : "memory");
}
__device__ __forceinline__ void mbar_expect_tx(uint32_t a, uint32_t bytes) {
    asm volatile("mbarrier.arrive.expect_tx.shared.b64 _, [%0], %1;"
                 :: "r"(a), "r"(bytes) : "memory");
}
__device__ __forceinline__ void tma_bulk_g2s(uint32_t dst, const void* src,
                                             uint32_t bytes, uint32_t mbar) {
    asm volatile(
        "cp.async.bulk.shared::cta.global.mbarrier::complete_tx::bytes "
        "[%0], [%1], %2, [%3];"
        :: "r"(dst), "l"(src), "r"(bytes), "r"(mbar) : "memory");
}
#define MBAR_WAIT(mbar, parity) do { \
    asm volatile( \
        "{\n\t.reg .pred P1;\n\t" \
        "WAIT_LOOP_%=:\n\t" \
        "mbarrier.try_wait.parity.acquire.cta.shared::cta.b64 P1, [%0], %1, 0x989680;\n\t" \
        "@P1 bra.uni WAIT_DONE_%=;\n\t" \
        "bra.uni WAIT_LOOP_%=;\n\t" \
        "WAIT_DONE_%=:\n\t}" \
        :: "r"(mbar), "r"(parity) : "memory"); \
} while (0)

__device__ __forceinline__ void arm_half(uint32_t mbar, uint32_t dst_base,
                                         const float* src_base) {
    mbar_expect_tx(mbar, HALF_BYTES);
    #pragma unroll
    for (int c = 0; c < CHUNKS; ++c) {
        tma_bulk_g2s(dst_base + c * CHUNK_B,
                     src_base + c * (CHUNK_B / 4), CHUNK_B, mbar);
    }
}

__global__ __launch_bounds__(TPB, 1)
void entmax_kernel(const float* __restrict__ z, float* __restrict__ out,
                   int rows) {
    __shared__ float    s_f[32];      // max partials
    __shared__ float    s_g[32];      // vmax partials
    __shared__ int      s_i[32];      // fallback count partials
    __shared__ float    s_h[32];      // fallback sum partials
    __shared__ float    s_cand[CAP];
    __shared__ int      s_cnt;
    __shared__ int      s_nxt;        // next-row ticket broadcast
    __shared__ int      s_bK;
    __shared__ float    s_bS, s_bV;
    __shared__ uint64_t s_mb[2];
    extern __shared__ float4 s_buf[]; // NV float4 = 125 KB

    const int tid  = threadIdx.x;
    const int lane = tid & 31;
    const int wid  = tid >> 5;
    const int grid = gridDim.x;

    const uint32_t mbL = smem_u32(&s_mb[0]);
    const uint32_t mbH = smem_u32(&s_mb[1]);
    const uint32_t bufL = smem_u32(s_buf);
    const uint32_t bufH = bufL + HALF_BYTES;

    if (tid == 0) { mbar_init(mbL, 1); mbar_init(mbH, 1); }
    __syncthreads();

    int cur = blockIdx.x;
    if (cur < rows && tid == 0) {
        s_nxt = grid + atomicAdd(&g_next, 1);      // ticket for NEXT row
        const float* row0 = z + (long long)cur * NC;
        arm_half(mbL, bufL, row0);
        arm_half(mbH, bufH, row0 + 4 * NVH_);
    }
    __syncthreads();
    int nxt = (cur < rows) ? s_nxt : rows;

    int it = 0;
    while (cur < rows) {
        const uint32_t par = (uint32_t)(it & 1);
        const bool have_next = (nxt < rows);
        const float* nrow = z + (long long)nxt * NC;

        float4 r[VPT];
        float lmax = NEG;

        // ---- lower half: wait, copy (fused max), re-arm for next row ----
        MBAR_WAIT(mbL, par);
        #pragma unroll
        for (int j = 0; j < VPH; ++j) {
            const int f = tid + j * TPB;
            if (f < NVH_) {
                float4 v = s_buf[f];
                r[j] = v;
                lmax = fmaxf(lmax, fmaxf(fmaxf(v.x, v.y), fmaxf(v.z, v.w)));
            } else {
                r[j] = make_float4(NEG, NEG, NEG, NEG);
            }
        }
        __syncthreads();                   // lower-half reads done
        if (tid == 0) {
            asm volatile("fence.proxy.async.shared::cta;" ::: "memory");
            if (have_next) arm_half(mbL, bufL, nrow);
        }

        // ---- upper half: wait, copy (fused max), re-arm; fetch ticket ----
        MBAR_WAIT(mbH, par);
        #pragma unroll
        for (int j = 0; j < VPH; ++j) {
            const int f = tid + j * TPB;
            if (f < NVH_) {
                float4 v = s_buf[NVH_ + f];
                r[VPH + j] = v;
                lmax = fmaxf(lmax, fmaxf(fmaxf(v.x, v.y), fmaxf(v.z, v.w)));
            } else {
                r[VPH + j] = make_float4(NEG, NEG, NEG, NEG);
            }
        }
        __syncthreads();                   // upper-half reads done
        if (tid == 0) {
            asm volatile("fence.proxy.async.shared::cta;" ::: "memory");
            if (have_next) arm_half(mbH, bufH, nrow + 4 * NVH_);
            s_cnt = 0;
            s_nxt = have_next ? (grid + atomicAdd(&g_next, 1)) : rows;
        }

        // ---- max reduce: publish once; every warp finishes privately ----
        #pragma unroll
        for (int o = 16; o; o >>= 1)
            lmax = fmaxf(lmax, __shfl_xor_sync(0xffffffffu, lmax, o));
        if (lane == 0) s_f[wid] = lmax;
        __syncthreads();                   // partials + s_cnt + s_nxt visible
        float m = s_f[lane];
        #pragma unroll
        for (int o = 16; o; o >>= 1)
            m = fmaxf(m, __shfl_xor_sync(0xffffffffu, m, o));
        const float tau0 = m - 1.0f;

        // ---- filter via max-tree pre-test ----
        float vmax = NEG;
        #pragma unroll
        for (int j = 0; j < VPT; ++j) {
            const float4 v = r[j];
            const float m4 = fmaxf(fmaxf(v.x, v.y), fmaxf(v.z, v.w));
            if (m4 > tau0) {
                float c;
                c = v.x; if (c > tau0) { int p = atomicAdd(&s_cnt, 1); if (p < CAP) s_cand[p] = c; } else vmax = fmaxf(vmax, c);
                c = v.y; if (c > tau0) { int p = atomicAdd(&s_cnt, 1); if (p < CAP) s_cand[p] = c; } else vmax = fmaxf(vmax, c);
                c = v.z; if (c > tau0) { int p = atomicAdd(&s_cnt, 1); if (p < CAP) s_cand[p] = c; } else vmax = fmaxf(vmax, c);
                c = v.w; if (c > tau0) { int p = atomicAdd(&s_cnt, 1); if (p < CAP) s_cand[p] = c; } else vmax = fmaxf(vmax, c);
            } else {
                vmax = fmaxf(vmax, m4);
            }
        }
        #pragma unroll
        for (int o = 16; o; o >>= 1)
            vmax = fmaxf(vmax, __shfl_xor_sync(0xffffffffu, vmax, o));
        if (lane == 0) s_g[wid] = vmax;
        __syncthreads();                   // cand/cnt/vmax visible
        const int cnt = s_cnt;
        float tau_ref;

        if (cnt <= CAP) {
            // ---- ALL warps run Newton redundantly (identical result);
            //      no publish barrier needed ----
            float gv = s_g[lane];
            #pragma unroll
            for (int o = 16; o; o >>= 1)
                gv = fmaxf(gv, __shfl_xor_sync(0xffffffffu, gv, o));

            float tl = tau0;
            int   kp = -1;
            int   kF = 1; float SF = 0.0f; float vcF = NEG;
            for (int itr = 0; itr < 64; ++itr) {
                int k = 0; float S = 0.0f; float vc = NEG;
                for (int i = lane; i < cnt; i += 32) {
                    const float c = s_cand[i];
                    if (c > tl) { k++; S += c; } else vc = fmaxf(vc, c);
                }
                #pragma unroll
                for (int o = 16; o; o >>= 1) {
                    k += __shfl_xor_sync(0xffffffffu, k, o);
                    S += __shfl_xor_sync(0xffffffffu, S, o);
                    vc = fmaxf(vc, __shfl_xor_sync(0xffffffffu, vc, o));
                }
                kF = k; SF = S; vcF = vc;
                if (k == kp) break;        // support fixed point
                kp = k;
                tl = (S - 1.0f) / (float)k;
            }
            // reference quirk: cs[k_max] = S + max{z <= tau_final}
            const float vfin = fmaxf(vcF, gv);
            const float vt = (vfin > -1e29f) ? vfin : 0.0f;
            tau_ref = (SF + vt - 1.0f) / (float)kF;
        } else {
            // ---- fallback: block-wide Newton over register data ----
            float tau = tau0;
            int kprev = -1;
            tau_ref = 0.0f;
            for (int fit = 0; fit < 64; ++fit) {
                int k = 0; float S = 0.0f; float v = NEG;
                #pragma unroll
                for (int j = 0; j < VPT; ++j) {
                    float c;
                    c = r[j].x; if (c > tau) { k++; S += c; } else v = fmaxf(v, c);
                    c = r[j].y; if (c > tau) { k++; S += c; } else v = fmaxf(v, c);
                    c = r[j].z; if (c > tau) { k++; S += c; } else v = fmaxf(v, c);
                    c = r[j].w; if (c > tau) { k++; S += c; } else v = fmaxf(v, c);
                }
                #pragma unroll
                for (int o = 16; o; o >>= 1) {
                    k += __shfl_xor_sync(0xffffffffu, k, o);
                    S += __shfl_xor_sync(0xffffffffu, S, o);
                    v  = fmaxf(v, __shfl_xor_sync(0xffffffffu, v, o));
                }
                if (lane == 0) { s_i[wid] = k; s_h[wid] = S; s_g[wid] = v; }
                __syncthreads();
                if (tid < 32) {
                    int kk = s_i[tid]; float SS = s_h[tid]; float vv = s_g[tid];
                    #pragma unroll
                    for (int o = 16; o; o >>= 1) {
                        kk += __shfl_xor_sync(0xffffffffu, kk, o);
                        SS += __shfl_xor_sync(0xffffffffu, SS, o);
                        vv  = fmaxf(vv, __shfl_xor_sync(0xffffffffu, vv, o));
                    }
                    if (tid == 0) { s_bK = kk; s_bS = SS; s_bV = vv; }
                }
                __syncthreads();
                const int   K  = s_bK;
                const float Sa = s_bS;
                const float Va = s_bV;
                if (K == kprev || fit == 63) {
                    const float vt = (Va > -1e29f) ? Va : 0.0f;
                    tau_ref = (Sa + vt - 1.0f) / (float)K;
                    break;
                }
                kprev = K;
                tau = (Sa - 1.0f) / (float)K;
                __syncthreads();
            }
        }

        // ---- output: relu(z - tau_ref)^1.5 from registers ----
        float4* orow = (float4*)(out + (long long)cur * NC);
        #pragma unroll
        for (int h = 0; h < 2; ++h) {
            #pragma unroll
            for (int j = 0; j < VPH; ++j) {
                const int f = tid + j * TPB;
                if (f < NVH_) {
                    const float4 v = r[h * VPH + j];
                    float a = v.x - tau_ref, bb = v.y - tau_ref;
                    float c = v.z - tau_ref, d = v.w - tau_ref;
                    float4 o;
                    if (fmaxf(fmaxf(a, bb), fmaxf(c, d)) > 0.0f) {
                        a = fmaxf(a, 0.0f); bb = fmaxf(bb, 0.0f);
                        c = fmaxf(c, 0.0f); d = fmaxf(d, 0.0f);
                        o.x = a * sqrtf(a);  o.y = bb * sqrtf(bb);
                        o.z = c * sqrtf(c);  o.w = d * sqrtf(d);
                    } else {
                        o.x = 0.0f; o.y = 0.0f; o.z = 0.0f; o.w = 0.0f;
                    }
                    __stcs(&orow[h * NVH_ + f], o);
                }
            }
        }

        cur = nxt;
        nxt = s_nxt;        // ticket fetched this iteration (safe: next write
                            // is after next iteration's copy barriers)
        ++it;
    }

    // ---- replay reset: last CTA to finish zeroes the ticket counters ----
    if (tid == 0) {
        __threadfence();
        const int d = atomicAdd(&g_done, 1);
        if (d == grid - 1) {
            g_next = 0;
            __threadfence();
            g_done = 0;
        }
    }
}

extern "C" void kernel_launch(void* const* d_in, const int* in_sizes, int n_in,
                              void* d_out, int out_size) {
    const float* z = (const float*)d_in[0];
    float* out = (float*)d_out;
    const int rows = in_sizes[0] / NC;

    int dev = 0, sms = 148;
    cudaGetDevice(&dev);
    cudaDeviceGetAttribute(&sms, cudaDevAttrMultiProcessorCount, dev);
    cudaFuncSetAttribute(entmax_kernel,
                         cudaFuncAttributeMaxDynamicSharedMemorySize, NV * 16);

    const int grid = (rows < sms) ? rows : sms;
    entmax_kernel<<<grid, TPB, NV * 16>>>(z, out, rows);
}

// round 12
// speedup vs baseline: 1.0922x; 1.0922x over previous
#include <cuda_runtime.h>
#include <cstdint>

// Entmax (alpha=1.5) per row, B=2048 x N=32000 fp32.
// v11 = v9 core (single 125 KB smem buffer, in-place half-row TMA re-arm,
// chunked bulk copies, max-tree filter, WARP-0 Newton + publish barrier)
// + dynamic row tickets only (v10 lesson: all-warp redundant Newton saturates
// issue slots and slows the store stream; keep serial work on one warp).

#define NC        32000
#define NV        (NC / 4)       // 8000 float4
#define NVH_      4000           // float4 per half
#define TPB       1024
#define VPT       8
#define VPH       4
#define CAP       1024
#define NEG       (-1e30f)
#define HALF_BYTES 64000
#define CHUNKS    4
#define CHUNK_B   (HALF_BYTES / CHUNKS)   // 16000

__device__ int g_next = 0;   // row tickets beyond the first wave
__device__ int g_done = 0;   // CTA completion count (replay reset)

__device__ __forceinline__ uint32_t smem_u32(const void* p) {
    uint32_t a;
    asm("{ .reg .u64 t; cvta.to.shared.u64 t, %1; cvt.u32.u64 %0, t; }"
        : "=r"(a) : "l"(p));
    return a;
}
__device__ __forceinline__ void mbar_init(uint32_t a, uint32_t cnt) {
    asm volatile("mbarrier.init.shared.b64 [%0], %1;" :: "r"(a), "r"(cnt) : "memory");
}
__device__ __forceinline__ void mbar_expect_tx(uint32_t a, uint32_t bytes) {
    asm volatile("mbarrier.arrive.expect_tx.shared.b64 _, [%0], %1;"
                 :: "r"(a), "r"(bytes) : "memory");
}
__device__ __forceinline__ void tma_bulk_g2s(uint32_t dst, const void* src,
                                             uint32_t bytes, uint32_t mbar) {
    asm volatile(
        "cp.async.bulk.shared::cta.global.mbarrier::complete_tx::bytes "
        "[%0], [%1], %2, [%3];"
        :: "r"(dst), "l"(src), "r"(bytes), "r"(mbar) : "memory");
}
#define MBAR_WAIT(mbar, parity) do { \
    asm volatile( \
        "{\n\t.reg .pred P1;\n\t" \
        "WAIT_LOOP_%=:\n\t" \
        "mbarrier.try_wait.parity.acquire.cta.shared::cta.b64 P1, [%0], %1, 0x989680;\n\t" \
        "@P1 bra.uni WAIT_DONE_%=;\n\t" \
        "bra.uni WAIT_LOOP_%=;\n\t" \
        "WAIT_DONE_%=:\n\t}" \
        :: "r"(mbar), "r"(parity) : "memory"); \
} while (0)

__device__ __forceinline__ void arm_half(uint32_t mbar, uint32_t dst_base,
                                         const float* src_base) {
    mbar_expect_tx(mbar, HALF_BYTES);
    #pragma unroll
    for (int c = 0; c < CHUNKS; ++c) {
        tma_bulk_g2s(dst_base + c * CHUNK_B,
                     src_base + c * (CHUNK_B / 4), CHUNK_B, mbar);
    }
}

__global__ __launch_bounds__(TPB, 1)
void entmax_kernel(const float* __restrict__ z, float* __restrict__ out,
                   int rows) {
    __shared__ float    s_f[32];      // max partials
    __shared__ float    s_g[32];      // vmax partials
    __shared__ int      s_i[32];      // fallback count partials
    __shared__ float    s_h[32];      // fallback sum partials
    __shared__ float    s_cand[CAP];
    __shared__ int      s_cnt;
    __shared__ int      s_nxt;        // next-row ticket broadcast
    __shared__ float    s_tauref;
    __shared__ int      s_bK;
    __shared__ float    s_bS, s_bV;
    __shared__ uint64_t s_mb[2];
    extern __shared__ float4 s_buf[]; // NV float4 = 125 KB

    const int tid  = threadIdx.x;
    const int lane = tid & 31;
    const int wid  = tid >> 5;
    const int grid = gridDim.x;

    const uint32_t mbL = smem_u32(&s_mb[0]);
    const uint32_t mbH = smem_u32(&s_mb[1]);
    const uint32_t bufL = smem_u32(s_buf);
    const uint32_t bufH = bufL + HALF_BYTES;

    if (tid == 0) { mbar_init(mbL, 1); mbar_init(mbH, 1); }
    __syncthreads();

    int cur = blockIdx.x;
    if (cur < rows && tid == 0) {
        s_nxt = grid + atomicAdd(&g_next, 1);      // ticket for NEXT row
        const float* row0 = z + (long long)cur * NC;
        arm_half(mbL, bufL, row0);
        arm_half(mbH, bufH, row0 + 4 * NVH_);
    }
    __syncthreads();
    int nxt = (cur < rows) ? s_nxt : rows;

    int it = 0;
    while (cur < rows) {
        const uint32_t par = (uint32_t)(it & 1);
        const bool have_next = (nxt < rows);
        const float* nrow = z + (long long)nxt * NC;

        float4 r[VPT];
        float lmax = NEG;

        // ---- lower half: wait, copy (fused max), re-arm for next row ----
        MBAR_WAIT(mbL, par);
        #pragma unroll
        for (int j = 0; j < VPH; ++j) {
            const int f = tid + j * TPB;
            if (f < NVH_) {
                float4 v = s_buf[f];
                r[j] = v;
                lmax = fmaxf(lmax, fmaxf(fmaxf(v.x, v.y), fmaxf(v.z, v.w)));
            } else {
                r[j] = make_float4(NEG, NEG, NEG, NEG);
            }
        }
        __syncthreads();                   // lower-half reads done
        if (tid == 0) {
            asm volatile("fence.proxy.async.shared::cta;" ::: "memory");
            if (have_next) arm_half(mbL, bufL, nrow);
        }

        // ---- upper half: wait, copy (fused max), re-arm; fetch ticket ----
        MBAR_WAIT(mbH, par);
        #pragma unroll
        for (int j = 0; j < VPH; ++j) {
            const int f = tid + j * TPB;
            if (f < NVH_) {
                float4 v = s_buf[NVH_ + f];
                r[VPH + j] = v;
                lmax = fmaxf(lmax, fmaxf(fmaxf(v.x, v.y), fmaxf(v.z, v.w)));
            } else {
                r[VPH + j] = make_float4(NEG, NEG, NEG, NEG);
            }
        }
        __syncthreads();                   // upper-half reads done
        if (tid == 0) {
            asm volatile("fence.proxy.async.shared::cta;" ::: "memory");
            if (have_next) arm_half(mbH, bufH, nrow + 4 * NVH_);
            s_cnt = 0;
            s_nxt = have_next ? (grid + atomicAdd(&g_next, 1)) : rows;
        }

        // ---- max reduce: publish once; every warp finishes privately ----
        #pragma unroll
        for (int o = 16; o; o >>= 1)
            lmax = fmaxf(lmax, __shfl_xor_sync(0xffffffffu, lmax, o));
        if (lane == 0) s_f[wid] = lmax;
        __syncthreads();                   // partials + s_cnt + s_nxt visible
        float m = s_f[lane];
        #pragma unroll
        for (int o = 16; o; o >>= 1)
            m = fmaxf(m, __shfl_xor_sync(0xffffffffu, m, o));
        const float tau0 = m - 1.0f;

        // ---- filter via max-tree pre-test ----
        float vmax = NEG;
        #pragma unroll
        for (int j = 0; j < VPT; ++j) {
            const float4 v = r[j];
            const float m4 = fmaxf(fmaxf(v.x, v.y), fmaxf(v.z, v.w));
            if (m4 > tau0) {
                float c;
                c = v.x; if (c > tau0) { int p = atomicAdd(&s_cnt, 1); if (p < CAP) s_cand[p] = c; } else vmax = fmaxf(vmax, c);
                c = v.y; if (c > tau0) { int p = atomicAdd(&s_cnt, 1); if (p < CAP) s_cand[p] = c; } else vmax = fmaxf(vmax, c);
                c = v.z; if (c > tau0) { int p = atomicAdd(&s_cnt, 1); if (p < CAP) s_cand[p] = c; } else vmax = fmaxf(vmax, c);
                c = v.w; if (c > tau0) { int p = atomicAdd(&s_cnt, 1); if (p < CAP) s_cand[p] = c; } else vmax = fmaxf(vmax, c);
            } else {
                vmax = fmaxf(vmax, m4);
            }
        }
        #pragma unroll
        for (int o = 16; o; o >>= 1)
            vmax = fmaxf(vmax, __shfl_xor_sync(0xffffffffu, vmax, o));
        if (lane == 0) s_g[wid] = vmax;
        __syncthreads();                   // cand/cnt/vmax visible
        const int cnt = s_cnt;
        float tau_ref;

        if (cnt <= CAP) {
            // ---- warp 0 only: private vmax reduce + Newton (v9 proven) ----
            if (wid == 0) {
                float gv = s_g[lane];
                #pragma unroll
                for (int o = 16; o; o >>= 1)
                    gv = fmaxf(gv, __shfl_xor_sync(0xffffffffu, gv, o));

                float tl = tau0;
                int   kp = -1;
                int   kF = 1; float SF = 0.0f; float vcF = NEG;
                for (int itr = 0; itr < 64; ++itr) {
                    int k = 0; float S = 0.0f; float vc = NEG;
                    for (int i = lane; i < cnt; i += 32) {
                        const float c = s_cand[i];
                        if (c > tl) { k++; S += c; } else vc = fmaxf(vc, c);
                    }
                    #pragma unroll
                    for (int o = 16; o; o >>= 1) {
                        k += __shfl_xor_sync(0xffffffffu, k, o);
                        S += __shfl_xor_sync(0xffffffffu, S, o);
                        vc = fmaxf(vc, __shfl_xor_sync(0xffffffffu, vc, o));
                    }
                    kF = k; SF = S; vcF = vc;
                    if (k == kp) break;    // support fixed point
                    kp = k;
                    tl = (S - 1.0f) / (float)k;
                }
                // reference quirk: cs[k_max] = S + max{z <= tau_final}
                const float vfin = fmaxf(vcF, gv);
                const float vt = (vfin > -1e29f) ? vfin : 0.0f;
                if (lane == 0) s_tauref = (SF + vt - 1.0f) / (float)kF;
            }
            __syncthreads();               // tau_ref published
            tau_ref = s_tauref;
        } else {
            // ---- fallback: block-wide Newton over register data ----
            float tau = tau0;
            int kprev = -1;
            tau_ref = 0.0f;
            for (int fit = 0; fit < 64; ++fit) {
                int k = 0; float S = 0.0f; float v = NEG;
                #pragma unroll
                for (int j = 0; j < VPT; ++j) {
                    float c;
                    c = r[j].x; if (c > tau) { k++; S += c; } else v = fmaxf(v, c);
                    c = r[j].y; if (c > tau) { k++; S += c; } else v = fmaxf(v, c);
                    c = r[j].z; if (c > tau) { k++; S += c; } else v = fmaxf(v, c);
                    c = r[j].w; if (c > tau) { k++; S += c; } else v = fmaxf(v, c);
                }
                #pragma unroll
                for (int o = 16; o; o >>= 1) {
                    k += __shfl_xor_sync(0xffffffffu, k, o);
                    S += __shfl_xor_sync(0xffffffffu, S, o);
                    v  = fmaxf(v, __shfl_xor_sync(0xffffffffu, v, o));
                }
                if (lane == 0) { s_i[wid] = k; s_h[wid] = S; s_g[wid] = v; }
                __syncthreads();
                if (tid < 32) {
                    int kk = s_i[tid]; float SS = s_h[tid]; float vv = s_g[tid];
                    #pragma unroll
                    for (int o = 16; o; o >>= 1) {
                        kk += __shfl_xor_sync(0xffffffffu, kk, o);
                        SS += __shfl_xor_sync(0xffffffffu, SS, o);
                        vv  = fmaxf(vv, __shfl_xor_sync(0xffffffffu, vv, o));
                    }
                    if (tid == 0) { s_bK = kk; s_bS = SS; s_bV = vv; }
                }
                __syncthreads();
                const int   K  = s_bK;
                const float Sa = s_bS;
                const float Va = s_bV;
                if (K == kprev || fit == 63) {
                    const float vt = (Va > -1e29f) ? Va : 0.0f;
                    tau_ref = (Sa + vt - 1.0f) / (float)K;
                    break;
                }
                kprev = K;
                tau = (Sa - 1.0f) / (float)K;
                __syncthreads();
            }
        }

        // ---- output: relu(z - tau_ref)^1.5 from registers ----
        float4* orow = (float4*)(out + (long long)cur * NC);
        #pragma unroll
        for (int h = 0; h < 2; ++h) {
            #pragma unroll
            for (int j = 0; j < VPH; ++j) {
                const int f = tid + j * TPB;
                if (f < NVH_) {
                    const float4 v = r[h * VPH + j];
                    float a = v.x - tau_ref, bb = v.y - tau_ref;
                    float c = v.z - tau_ref, d = v.w - tau_ref;
                    float4 o;
                    if (fmaxf(fmaxf(a, bb), fmaxf(c, d)) > 0.0f) {
                        a = fmaxf(a, 0.0f); bb = fmaxf(bb, 0.0f);
                        c = fmaxf(c, 0.0f); d = fmaxf(d, 0.0f);
                        o.x = a * sqrtf(a);  o.y = bb * sqrtf(bb);
                        o.z = c * sqrtf(c);  o.w = d * sqrtf(d);
                    } else {
                        o.x = 0.0f; o.y = 0.0f; o.z = 0.0f; o.w = 0.0f;
                    }
                    __stcs(&orow[h * NVH_ + f], o);
                }
            }
        }

        cur = nxt;
        nxt = s_nxt;        // fetched under barrier (2) this iteration
        ++it;
    }

    // ---- replay reset: last CTA zeroes the ticket counters ----
    if (tid == 0) {
        __threadfence();
        const int d = atomicAdd(&g_done, 1);
        if (d == grid - 1) {
            g_next = 0;
            __threadfence();
            g_done = 0;
        }
    }
}

extern "C" void kernel_launch(void* const* d_in, const int* in_sizes, int n_in,
                              void* d_out, int out_size) {
    const float* z = (const float*)d_in[0];
    float* out = (float*)d_out;
    const int rows = in_sizes[0] / NC;

    int dev = 0, sms = 148;
    cudaGetDevice(&dev);
    cudaDeviceGetAttribute(&sms, cudaDevAttrMultiProcessorCount, dev);
    cudaFuncSetAttribute(entmax_kernel,
                         cudaFuncAttributeMaxDynamicSharedMemorySize, NV * 16);

    const int grid = (rows < sms) ? rows : sms;
    entmax_kernel<<<grid, TPB, NV * 16>>>(z, out, rows);
}